// round 10
// baseline (speedup 1.0000x reference)
#include <cuda_runtime.h>
#include <math.h>

#define N_BOX     1048576
#define NUM_PTS   9
#define L_CONST   3.0f
#define EPS_F     1e-6f
#define GMM_EPS_F 1e-6f

#define BOX_PER_WCHUNK 32
#define WPRED_F4   (BOX_PER_WCHUNK * 18 / 4)   // 144 float4 per chunk
#define NSTAGE     3
#define NWCHUNK    (N_BOX / BOX_PER_WCHUNK)    // 32768
#define GRID_BLKS  592                         // 4 * 148, persistent single wave
#define WARPS_PER_BLK 8
#define TOTAL_WARPS  (GRID_BLKS * WARPS_PER_BLK)   // 4736

__global__ void zero_out_kernel(float* out) { out[0] = 0.0f; }

__device__ __forceinline__ void cp_async16(void* smem_ptr, const void* gptr) {
    unsigned saddr = (unsigned)__cvta_generic_to_shared(smem_ptr);
    asm volatile("cp.async.cg.shared.global [%0], [%1], 16;\n"
                 :: "r"(saddr), "l"(gptr));
}
__device__ __forceinline__ void cp_commit() {
    asm volatile("cp.async.commit_group;\n" ::: "memory");
}
template <int N>
__device__ __forceinline__ void cp_wait() {
    asm volatile("cp.async.wait_group %0;\n" :: "n"(N) : "memory");
}

// Warp-cooperative staging of one 32-box pred chunk (144 float4).
__device__ __forceinline__ void issue_pred(float4* st, const float4* gp, int lane) {
    #pragma unroll
    for (int j = 0; j < 4; j++)
        cp_async16(&st[lane + 32 * j], &gp[lane + 32 * j]);
    if (lane < WPRED_F4 - 4 * 32)                       // remaining 16
        cp_async16(&st[lane + 128], &gp[lane + 128]);
    cp_commit();
}

__device__ __forceinline__ float box_loss(const float* s_pred, int lane,
                                          float4 ta, float4 tb) {
    const float2* p2 = reinterpret_cast<const float2*>(s_pred + lane * 18);
    float px[NUM_PTS], py[NUM_PTS];
    #pragma unroll
    for (int k = 0; k < NUM_PTS; k++) {
        float2 v = p2[k];
        px[k] = v.x; py[k] = v.y;
    }

    float sx = 0.f, sy = 0.f;
    #pragma unroll
    for (int k = 0; k < NUM_PTS; k++) { sx += px[k]; sy += py[k]; }
    const float inv_np = 1.0f / (float)NUM_PTS;
    float mux = sx * inv_np, muy = sy * inv_np;

    float cxx = 0.f, cxy = 0.f, cyy = 0.f;
    #pragma unroll
    for (int k = 0; k < NUM_PTS; k++) {
        float dx = px[k] - mux, dy = py[k] - muy;
        cxx += dx * dx; cxy += dx * dy; cyy += dy * dy;
    }
    cxx = cxx * inv_np + GMM_EPS_F;
    cxy = cxy * inv_np;
    cyy = cyy * inv_np + GMM_EPS_F;

    float tmux = (ta.x + ta.z + tb.x + tb.z) * 0.25f;
    float tmuy = (ta.y + ta.w + tb.y + tb.w) * 0.25f;

    float e1x = ta.z - ta.x, e1y = ta.w - ta.y;
    float e2x = tb.x - ta.z, e2y = tb.y - ta.w;
    float w = e1x * e1x + e1y * e1y;
    float h = e2x * e2x + e2y * e2y;
    float inv_sw = rsqrtf(w);
    float c = e1x * inv_sw, s = e1y * inv_sw;

    const float dscale = 1.0f / (4.0f * L_CONST * L_CONST);
    float d0 = w * dscale, d1 = h * dscale;

    float c2 = c * c, s2 = s * s, cs = c * s;
    float t00 = c2 * d0 + s2 * d1;
    float t01 = cs * (d0 - d1);
    float t11 = s2 * d0 + c2 * d1;

    float t_det = t00 * t11 - t01 * t01;
    float p_det = cxx * cyy - cxy * cxy;

    float inv_tdet = 1.0f / t_det;
    float i00 =  t11 * inv_tdet;
    float i01 = -t01 * inv_tdet;
    float i11 =  t00 * inv_tdet;

    float dx = mux - tmux, dy = muy - tmuy;
    float term1 = dx * (i00 * dx + i01 * dy) + dy * (i01 * dx + i11 * dy);
    float trace = i00 * cxx + 2.0f * i01 * cxy + i11 * cyy;

    float term2 = trace + logf(t_det / p_det);
    float kld = 0.5f * (term1 + term2) - 1.0f;
    float kl_agg = fmaxf(kld, EPS_F);
    return 1.0f - 1.0f / (2.0f + sqrtf(kl_agg));
}

__global__ void __launch_bounds__(256, 4) kld_loss_kernel(
    const float* __restrict__ pred,
    const float* __restrict__ target,
    float* __restrict__ out)
{
    // per-warp triple-buffered pred slabs: 8 * 3 * 144 float4 = 55296 B
    extern __shared__ float4 s4[];

    const int tid  = threadIdx.x;
    const int lane = tid & 31;
    const int wid  = tid >> 5;
    float4* wslab = s4 + wid * (NSTAGE * WPRED_F4);

    const float4* gp_base = reinterpret_cast<const float4*>(pred);
    const float4* gt_base = reinterpret_cast<const float4*>(target);

    int c = blockIdx.x * WARPS_PER_BLK + wid;   // < 4736 < NWCHUNK always

    // ---- prologue: 2 pred chunks in flight, current target in regs ----
    issue_pred(wslab, gp_base + (size_t)c * WPRED_F4, lane);
    {
        int c1 = c + TOTAL_WARPS;
        if (c1 < NWCHUNK)
            issue_pred(wslab + WPRED_F4, gp_base + (size_t)c1 * WPRED_F4, lane);
    }
    const float4* gt_cur = gt_base + (size_t)c * (BOX_PER_WCHUNK * 2) + lane * 2;
    float4 ta = gt_cur[0];
    float4 tb = gt_cur[1];

    float acc = 0.0f;
    int stage = 0;

    while (c < NWCHUNK) {
        const int next1 = c + TOTAL_WARPS;
        const int next2 = c + 2 * TOTAL_WARPS;

        // keep pipeline 2 deep
        if (next2 < NWCHUNK) {
            int s2 = stage + 2; if (s2 >= NSTAGE) s2 -= NSTAGE;
            issue_pred(wslab + s2 * WPRED_F4,
                       gp_base + (size_t)next2 * WPRED_F4, lane);
            cp_wait<2>();
        } else if (next1 < NWCHUNK) {
            cp_wait<1>();
        } else {
            cp_wait<0>();
        }
        __syncwarp();

        // register prefetch of next chunk's target (issues before compute)
        float4 tna, tnb;
        if (next1 < NWCHUNK) {
            const float4* gt_n = gt_base + (size_t)next1 * (BOX_PER_WCHUNK * 2) + lane * 2;
            tna = gt_n[0];
            tnb = gt_n[1];
        }

        const float* s_pred = reinterpret_cast<const float*>(wslab + stage * WPRED_F4);
        acc += box_loss(s_pred, lane, ta, tb);

        ta = tna; tb = tnb;
        __syncwarp();

        c = next1;
        stage++; if (stage >= NSTAGE) stage -= NSTAGE;
    }

    // ---- block reduction ----
    #pragma unroll
    for (int off = 16; off > 0; off >>= 1)
        acc += __shfl_down_sync(0xFFFFFFFFu, acc, off);

    __shared__ float warp_sums[WARPS_PER_BLK];
    if (lane == 0) warp_sums[wid] = acc;
    __syncthreads();

    if (wid == 0) {
        float v = (lane < WARPS_PER_BLK) ? warp_sums[lane] : 0.0f;
        #pragma unroll
        for (int off = 4; off > 0; off >>= 1)
            v += __shfl_down_sync(0xFFFFFFFFu, v, off);
        if (lane == 0)
            atomicAdd(out, v * (1.0f / (float)N_BOX));
    }
}

extern "C" void kernel_launch(void* const* d_in, const int* in_sizes, int n_in,
                              void* d_out, int out_size) {
    const float* pred   = (const float*)d_in[0];
    const float* target = (const float*)d_in[1];
    float* out = (float*)d_out;

    static int configured = 0;
    if (!configured) {
        cudaFuncSetAttribute(kld_loss_kernel,
                             cudaFuncAttributeMaxDynamicSharedMemorySize,
                             WARPS_PER_BLK * NSTAGE * WPRED_F4 * sizeof(float4));
        configured = 1;
    }

    zero_out_kernel<<<1, 1>>>(out);
    kld_loss_kernel<<<GRID_BLKS, 256,
                      WARPS_PER_BLK * NSTAGE * WPRED_F4 * sizeof(float4)>>>(
        pred, target, out);
}